// round 17
// baseline (speedup 1.0000x reference)
#include <cuda_runtime.h>
#include <cuda_fp16.h>
#include <math.h>
#include <stdint.h>

// ---------------- problem constants (fixed-shape problem) ----------------
#define T_TOK 8192
#define DIM   2048
#define HID   8192
#define EPS_P 1e-4f
#define RMS_EPS 1e-5f

// fp16 smem tile: rows x 32 halves, row stride 40 halves (80B, conflict-free)
#define SKH   40
#define GN    16      // band width (n-tiles) for the L2 swizzle
#define LOSC  4096.0f          // lo-part pre-scale (2^12)
#define LOSCI 2.44140625e-4f   // 2^-12

// ---------------- scratch (static device globals; no allocs) -------------
__device__ __half g_xhi [(size_t)T_TOK * DIM];
__device__ __half g_xlo [(size_t)T_TOK * DIM];          // scaled by 2^12
__device__ __half g_wqth[(size_t)DIM * DIM];
__device__ __half g_wqtl[(size_t)DIM * DIM];            // scaled by 2^12
__device__ __half g_wkth[(size_t)DIM * DIM];
__device__ __half g_wktl[(size_t)DIM * DIM];            // scaled by 2^12
__device__ __half g_fc1t[(size_t)2 * HID * DIM];
__device__ __half g_fc2t[(size_t)DIM * HID];
__device__ __half g_xn [(size_t)T_TOK * DIM];
__device__ __half g_s  [(size_t)T_TOK * HID];
__device__ float  g_q  [(size_t)T_TOK * DIM];
__device__ float  g_k  [(size_t)T_TOK * DIM];
__device__ float  g_z  [(size_t)T_TOK * DIM];
__device__ float  g_nq [T_TOK];
__device__ float  g_nk [T_TOK];
__device__ float  g_dqk[T_TOK];
__device__ float  g_a  [T_TOK];
__device__ float  g_c  [T_TOK];

// ---------------- PTX helpers ----------------
__device__ __forceinline__ uint32_t smem_u32(const void* p) {
    uint32_t a;
    asm("{ .reg .u64 t; cvta.to.shared.u64 t, %1; cvt.u32.u64 %0, t; }" : "=r"(a) : "l"(p));
    return a;
}
__device__ __forceinline__ void cp16(uint32_t dst, const void* src) {
    asm volatile("cp.async.cg.shared.global [%0], [%1], 16;" :: "r"(dst), "l"(src) : "memory");
}
__device__ __forceinline__ void cp_commit() {
    asm volatile("cp.async.commit_group;" ::: "memory");
}
template<int N> __device__ __forceinline__ void cp_wait() {
    asm volatile("cp.async.wait_group %0;" :: "n"(N) : "memory");
}

// m16n8k16 row.col fp16 MMA, fp32 accumulate: D += A*B
#define MMAH(c, a, b0, b1)                                                      \
    asm volatile(                                                               \
        "mma.sync.aligned.m16n8k16.row.col.f32.f16.f16.f32 "                    \
        "{%0,%1,%2,%3}, {%4,%5,%6,%7}, {%8,%9}, {%0,%1,%2,%3};"                 \
        : "+f"((c)[0]), "+f"((c)[1]), "+f"((c)[2]), "+f"((c)[3])                \
        : "r"((a)[0]), "r"((a)[1]), "r"((a)[2]), "r"((a)[3]),                   \
          "r"(b0), "r"(b1))

// band swizzle: 1D grid -> (m_tile, n_tile); m fastest inside a GN-wide band
__device__ __forceinline__ void swz_tile(int bid, int tiles_m, int& mt, int& nt) {
    const int per_band = GN * tiles_m;
    const int band = bid / per_band;
    const int loc  = bid % per_band;
    mt = loc / GN;
    nt = band * GN + loc % GN;
}

// load A fragment (4 regs) for m16n8k16 from fp16 smem row-major (SKH stride)
__device__ __forceinline__ void frag_a(uint32_t* a, const __half* base,
                                       int r, int koff /*halves*/, int c) {
    const __half* p = base + r * SKH + koff + 2 * c;
    a[0] = *(const uint32_t*)(p);
    a[1] = *(const uint32_t*)(p + 8 * SKH);
    a[2] = *(const uint32_t*)(p + 8);
    a[3] = *(const uint32_t*)(p + 8 * SKH + 8);
}

// ============ unified fp16 GEMM, BM=128, multi-stage, 2 CTAs/SM ===========
// 256 threads, 8 warps as 4(M) x 2(N). Operands fp16 [rows][K] row-major.
// SPLIT (q/k): A2/Bt2 are 2^12-scaled lo parts; out = accH + 2^-12*accL.
// GLU (fc1):   BN=64 out cols; B rows [n0,+64)=hh, [HID+n0,+64)=g;
//              writes Ch = fp16(silu(g)*hh).
// plain (fc2): Cf = A@Bt^T + res (fp32).
template<int BN, bool SPLIT, bool GLU, int STAGES>
__global__ __launch_bounds__(256, 2)
void gemm16(const __half* __restrict__ A,  const __half* __restrict__ A2,
            const __half* __restrict__ Bt, const __half* __restrict__ Bt2,
            const float* __restrict__ res, float* __restrict__ Cf,
            __half* __restrict__ Ch, int N, int K, int tiles_m)
{
    constexpr int AR = SPLIT ? 256 : 128;
    constexpr int BR = SPLIT ? 2 * BN : (GLU ? 128 : BN);
    constexpr int SR = AR + BR;
    constexpr int STGH = SR * SKH;          // halves per stage
    constexpr int NH = GLU ? 2 : 1;
    constexpr int NT = GLU ? 4 : (BN / 16);
    constexpr int LITER = SR / 64;          // (SR*4 cp16) / 256 threads

    extern __shared__ __half smh[];
    const uint32_t sbase = smem_u32(smh);

    const int tid  = threadIdx.x;
    const int lane = tid & 31, wid = tid >> 5;
    const int warpM = wid & 3, warpN = wid >> 2;
    const int rgrp = lane >> 2, cg = lane & 3;

    int mti, nti;
    swz_tile(blockIdx.x, tiles_m, mti, nti);
    const int m0 = mti * 128;
    const int n0 = nti * BN;
    const int KT = K >> 5;                  // 32 k-halves per chunk

    auto load_stage = [&](int s, int kt) {
        const uint32_t st = sbase + (uint32_t)s * (STGH * 2);
        #pragma unroll
        for (int it = 0; it < LITER; ++it) {
            const int idx = tid + it * 256;
            const int r = idx >> 2, c8 = idx & 3;
            const uint32_t d = st + (uint32_t)(r * SKH + c8 * 8) * 2;
            const __half* src;
            if (r < 128) {
                src = A + (size_t)(m0 + r) * K;
            } else if (SPLIT && r < 256) {
                src = A2 + (size_t)(m0 + r - 128) * K;
            } else {
                const int rb = r - AR;
                if (SPLIT) {
                    src = (rb < BN) ? Bt  + (size_t)(n0 + rb) * K
                                    : Bt2 + (size_t)(n0 + rb - BN) * K;
                } else if (GLU) {
                    const int brow = (rb < 64) ? (n0 + rb) : (HID + n0 + rb - 64);
                    src = Bt + (size_t)brow * K;
                } else {
                    src = Bt + (size_t)(n0 + rb) * K;
                }
            }
            cp16(d, src + kt * 32 + c8 * 8);
        }
    };

    float accH[NH][2][NT][4];
    float accL[SPLIT ? 2 : 1][SPLIT ? NT : 1][4];
    #pragma unroll
    for (int h = 0; h < NH; ++h)
        #pragma unroll
        for (int mt = 0; mt < 2; ++mt)
            #pragma unroll
            for (int nt = 0; nt < NT; ++nt)
                #pragma unroll
                for (int j = 0; j < 4; ++j) accH[h][mt][nt][j] = 0.f;
    if (SPLIT) {
        #pragma unroll
        for (int mt = 0; mt < 2; ++mt)
            #pragma unroll
            for (int nt = 0; nt < NT; ++nt)
                #pragma unroll
                for (int j = 0; j < 4; ++j) accL[mt][nt][j] = 0.f;
    }

    // prologue: fill stages 0..STAGES-2
    #pragma unroll
    for (int s = 0; s < STAGES - 1; ++s) { load_stage(s, s); cp_commit(); }

    for (int kt = 0; kt < KT; ++kt) {
        cp_wait<STAGES - 2>();      // stage kt%STAGES resident (all groups <= kt)
        __syncthreads();            // + all warps done computing stage (kt-1)

        // refill the slot freed at iteration kt-1 with chunk kt+STAGES-1
        const int lkt = kt + STAGES - 1;
        if (lkt < KT) load_stage(lkt % STAGES, lkt);
        cp_commit();

        const __half* sA  = smh + (kt % STAGES) * STGH;
        const __half* sAl = sA + 128 * SKH;     // valid iff SPLIT
        const __half* sB  = sA + AR * SKH;

        #pragma unroll
        for (int ks = 0; ks < 2; ++ks) {
            const int koff = ks * 16;
            uint32_t aH[2][4], aL[2][4];
            #pragma unroll
            for (int mt = 0; mt < 2; ++mt) {
                const int r = warpM * 32 + mt * 16 + rgrp;
                frag_a(aH[mt], sA, r, koff, cg);
                if (SPLIT) frag_a(aL[mt], sAl, r, koff, cg);
            }
            #pragma unroll
            for (int h = 0; h < NH; ++h) {
                #pragma unroll
                for (int nt = 0; nt < NT; ++nt) {
                    const int n = (GLU ? (h * 64 + warpN * 32) : (warpN * (BN / 2)))
                                + nt * 8 + rgrp;
                    const __half* bp = sB + n * SKH + koff + 2 * cg;
                    const uint32_t bH0 = *(const uint32_t*)(bp);
                    const uint32_t bH1 = *(const uint32_t*)(bp + 8);
                    #pragma unroll
                    for (int mt = 0; mt < 2; ++mt)
                        MMAH(accH[h][mt][nt], aH[mt], bH0, bH1);
                    if (SPLIT) {
                        const __half* blp = bp + (size_t)BN * SKH;
                        const uint32_t bL0 = *(const uint32_t*)(blp);
                        const uint32_t bL1 = *(const uint32_t*)(blp + 8);
                        #pragma unroll
                        for (int mt = 0; mt < 2; ++mt) {
                            MMAH(accL[mt][nt], aL[mt], bH0, bH1);   // loS*hi
                            MMAH(accL[mt][nt], aH[mt], bL0, bL1);   // hi*loS
                        }
                    }
                }
            }
        }
    }

    // epilogue
    #pragma unroll
    for (int mt = 0; mt < 2; ++mt) {
        const int r = m0 + warpM * 32 + mt * 16 + rgrp;
        #pragma unroll
        for (int nt = 0; nt < NT; ++nt) {
            const int c = n0 + (GLU ? warpN * 32 : warpN * (BN / 2))
                        + nt * 8 + (cg << 1);
            if (GLU) {
                #pragma unroll
                for (int j = 0; j < 2; ++j) {   // j=0: row r, j=1: row r+8
                    const size_t o = (size_t)(r + j * 8) * N + c;
                    const float hh0 = accH[0][mt][nt][2 * j];
                    const float hh1 = accH[0][mt][nt][2 * j + 1];
                    const float gg0 = accH[1][mt][nt][2 * j];
                    const float gg1 = accH[1][mt][nt][2 * j + 1];
                    const float s0 = hh0 * (gg0 / (1.f + expf(-gg0)));
                    const float s1 = hh1 * (gg1 / (1.f + expf(-gg1)));
                    *(__half2*)(Ch + o) = __floats2half2_rn(s0, s1);
                }
            } else {
                float v[4];
                #pragma unroll
                for (int j = 0; j < 4; ++j)
                    v[j] = SPLIT ? accH[0][mt][nt][j] + accL[mt][nt][j] * LOSCI
                                 : accH[0][mt][nt][j];
                const size_t o0 = (size_t)r * N + c;
                const size_t o1 = (size_t)(r + 8) * N + c;
                float2 v0 = make_float2(v[0], v[1]);
                float2 v1 = make_float2(v[2], v[3]);
                if (res) {
                    const float2 d0 = *(const float2*)(res + o0);
                    const float2 d1 = *(const float2*)(res + o1);
                    v0.x += d0.x; v0.y += d0.y;
                    v1.x += d1.x; v1.y += d1.y;
                }
                *(float2*)(Cf + o0) = v0;
                *(float2*)(Cf + o1) = v1;
            }
        }
    }
}

// ---------------- pre-passes ----------------
// x -> fp16 hi + fp16 (lo * 2^12)
__global__ void split16(const float* __restrict__ x,
                        __half* __restrict__ hi, __half* __restrict__ lo)
{
    const size_t i = (size_t)blockIdx.x * blockDim.x + threadIdx.x;
    if (i >= (size_t)T_TOK * DIM) return;
    const float v = x[i];
    const __half h = __float2half_rn(v);
    hi[i] = h;
    lo[i] = __float2half_rn((v - __half2float(h)) * LOSC);
}

// W[K,N] -> Wt[N,K] fp16
__global__ void t16(const float* __restrict__ W, __half* __restrict__ Wt,
                    int K, int N)
{
    __shared__ float t[32][33];
    const int n0 = blockIdx.x * 32, k0 = blockIdx.y * 32;
    for (int i = threadIdx.y; i < 32; i += 8)
        t[i][threadIdx.x] = W[(size_t)(k0 + i) * N + n0 + threadIdx.x];
    __syncthreads();
    for (int i = threadIdx.y; i < 32; i += 8)
        Wt[(size_t)(n0 + i) * K + k0 + threadIdx.x] = __float2half_rn(t[threadIdx.x][i]);
}

// W[K,N] -> WtH[N,K] fp16 hi, WtL[N,K] fp16 (lo * 2^12)
__global__ void tsplit16(const float* __restrict__ W,
                         __half* __restrict__ WtH, __half* __restrict__ WtL,
                         int K, int N)
{
    __shared__ float t[32][33];
    const int n0 = blockIdx.x * 32, k0 = blockIdx.y * 32;
    for (int i = threadIdx.y; i < 32; i += 8)
        t[i][threadIdx.x] = W[(size_t)(k0 + i) * N + n0 + threadIdx.x];
    __syncthreads();
    for (int i = threadIdx.y; i < 32; i += 8) {
        const float v = t[threadIdx.x][i];
        const __half h = __float2half_rn(v);
        const size_t o = (size_t)(n0 + i) * K + k0 + threadIdx.x;
        WtH[o] = h;
        WtL[o] = __float2half_rn((v - __half2float(h)) * LOSC);
    }
}

// ---------------- block reduction helper ----------------
__device__ __forceinline__ float block_sum(float v, float* sm)
{
    #pragma unroll
    for (int o = 16; o > 0; o >>= 1) v += __shfl_down_sync(0xffffffffu, v, o);
    const int lane = threadIdx.x & 31, wid = threadIdx.x >> 5;
    if (lane == 0) sm[wid] = v;
    __syncthreads();
    v = (threadIdx.x < (blockDim.x >> 5)) ? sm[threadIdx.x] : 0.f;
    if (wid == 0) {
        #pragma unroll
        for (int o = 16; o > 0; o >>= 1) v += __shfl_down_sync(0xffffffffu, v, o);
    }
    return v;
}

// ---------------- rmsnorm (emits fp16 values) ----------------
__global__ void rmsnorm_kernel(const float* __restrict__ x,
                               const float* __restrict__ w,
                               __half* __restrict__ xn)
{
    __shared__ float sm[32];
    __shared__ float s_inv;
    const int row = blockIdx.x;
    const float* xr = x + (size_t)row * DIM;
    float ss = 0.f;
    for (int i = threadIdx.x; i < DIM; i += blockDim.x) {
        const float v = xr[i];
        ss = fmaf(v, v, ss);
    }
    ss = block_sum(ss, sm);
    if (threadIdx.x == 0) s_inv = rsqrtf(ss / (float)DIM + RMS_EPS);
    __syncthreads();
    const float inv = s_inv;
    __half* xo = xn + (size_t)row * DIM;
    for (int i = threadIdx.x; i < DIM; i += blockDim.x)
        xo[i] = __float2half_rn(xr[i] * inv * w[i]);
}

// ------- per-token stats: |q_t|^2, |k_t|^2, q_{t-1}.k_t -------------------
__global__ void qkstats_kernel(const float* __restrict__ q,
                               const float* __restrict__ k,
                               float* __restrict__ nq2,
                               float* __restrict__ nk2,
                               float* __restrict__ dqk)
{
    __shared__ float sm[32];
    const int t = blockIdx.x;
    const float* qr = q + (size_t)t * DIM;
    const float* kr = k + (size_t)t * DIM;
    float sq = 0.f, sk = 0.f, sd = 0.f;
    for (int i = threadIdx.x; i < DIM; i += blockDim.x) {
        const float qv = qr[i], kv = kr[i];
        sq = fmaf(qv, qv, sq);
        sk = fmaf(kv, kv, sk);
        if (t > 0) sd = fmaf(qr[i - DIM], kv, sd);
    }
    sq = block_sum(sq, sm);
    __syncthreads();
    sk = block_sum(sk, sm);
    __syncthreads();
    sd = block_sum(sd, sm);
    if (threadIdx.x == 0) {
        nq2[t] = sq;
        nk2[t] = sk;
        dqk[t] = (t > 0) ? sd : 0.f;
    }
}

// ------- boundary probs -> scan coefficients a_t, c_t ---------------------
__global__ void pcoef_kernel(const float* __restrict__ nq2,
                             const float* __restrict__ nk2,
                             const float* __restrict__ dqk,
                             const int* __restrict__ cu, int nseq,
                             float* __restrict__ a, float* __restrict__ c)
{
    const int t = blockIdx.x * blockDim.x + threadIdx.x;
    if (t >= T_TOK) return;
    bool ss = false;
    for (int i = 0; i < nseq; ++i) ss |= (cu[i] == t);
    float p;
    if (t == 0 || ss) {
        p = 1.0f;
    } else {
        const float cosv = dqk[t] * rsqrtf(nq2[t - 1] * nk2[t]);
        p = (1.0f - cosv) * 0.5f;
    }
    p = fminf(fmaxf(p, EPS_P), 1.0f - EPS_P);
    const bool b = (p >= 0.5f);
    a[t] = (ss || t == 0) ? 0.f : (b ? 1.f - p : 1.f);
    c[t] = b ? p : 0.f;
}

// ------- segmented EMA scan: h_t = a_t h_{t-1} + c_t z_t ------------------
__global__ void ema_scan_kernel(const float* __restrict__ z,
                                const float* __restrict__ a,
                                const float* __restrict__ c,
                                const int* __restrict__ cu,
                                float* __restrict__ out)
{
    __shared__ float sa[1024];
    __shared__ float sc[1024];
    const int seg = blockIdx.y;
    const int t0 = cu[seg], t1 = cu[seg + 1];
    const int ch = blockIdx.x * blockDim.x + threadIdx.x;
    float h = 0.f;
    for (int base = t0; base < t1; base += 1024) {
        const int len = min(1024, t1 - base);
        __syncthreads();
        for (int i = threadIdx.x; i < len; i += blockDim.x) {
            sa[i] = a[base + i];
            sc[i] = c[base + i];
        }
        __syncthreads();
        for (int i = 0; i < len; ++i) {
            const size_t off = (size_t)(base + i) * DIM + ch;
            const float zv = z[off];
            h = fmaf(sa[i], h, sc[i] * zv);
            out[off] = h;
        }
    }
}

// ---------------- launch ----------------
extern "C" void kernel_launch(void* const* d_in, const int* in_sizes, int n_in,
                              void* d_out, int out_size)
{
    const float* x      = (const float*)d_in[0];
    const float* Wq     = (const float*)d_in[1];
    const float* Wk     = (const float*)d_in[2];
    const float* fc1    = (const float*)d_in[3];
    const float* fc2    = (const float*)d_in[4];
    const float* norm_w = (const float*)d_in[5];
    const int*   cu     = (const int*)d_in[6];
    float*       out    = (float*)d_out;
    const int nseq = in_sizes[6] - 1;

    __half *xhi, *xlo, *wqth, *wqtl, *wkth, *wktl, *fc1t, *fc2t, *xn, *s;
    float *q, *k, *z, *nq, *nk, *dqk, *a, *c;
    cudaGetSymbolAddress((void**)&xhi,  g_xhi);
    cudaGetSymbolAddress((void**)&xlo,  g_xlo);
    cudaGetSymbolAddress((void**)&wqth, g_wqth);
    cudaGetSymbolAddress((void**)&wqtl, g_wqtl);
    cudaGetSymbolAddress((void**)&wkth, g_wkth);
    cudaGetSymbolAddress((void**)&wktl, g_wktl);
    cudaGetSymbolAddress((void**)&fc1t, g_fc1t);
    cudaGetSymbolAddress((void**)&fc2t, g_fc2t);
    cudaGetSymbolAddress((void**)&xn,   g_xn);
    cudaGetSymbolAddress((void**)&s,    g_s);
    cudaGetSymbolAddress((void**)&q,    g_q);
    cudaGetSymbolAddress((void**)&k,    g_k);
    cudaGetSymbolAddress((void**)&z,    g_z);
    cudaGetSymbolAddress((void**)&nq,   g_nq);
    cudaGetSymbolAddress((void**)&nk,   g_nk);
    cudaGetSymbolAddress((void**)&dqk,  g_dqk);
    cudaGetSymbolAddress((void**)&a,    g_a);
    cudaGetSymbolAddress((void**)&c,    g_c);

    // stage sizes (fp16, SKH=40): q/k 3 stages x 384 rows; others 4 x 256
    const int SMEM_QK = 3 * 384 * SKH * 2;   // 92160 B  -> 2 CTAs/SM (184 KB)
    const int SMEM_G  = 4 * 256 * SKH * 2;   // 81920 B  -> 2 CTAs/SM (164 KB)
    cudaFuncSetAttribute((const void*)gemm16<64, true, false, 3>,
                         cudaFuncAttributeMaxDynamicSharedMemorySize, SMEM_QK);
    cudaFuncSetAttribute((const void*)gemm16<64, false, true, 4>,
                         cudaFuncAttributeMaxDynamicSharedMemorySize, SMEM_G);
    cudaFuncSetAttribute((const void*)gemm16<128, false, false, 4>,
                         cudaFuncAttributeMaxDynamicSharedMemorySize, SMEM_G);

    // ---- pre-passes: fp16 splits + transposed fp16 weights ----
    {
        const size_t n = (size_t)T_TOK * DIM;
        split16<<<(unsigned)((n + 255) / 256), 256>>>(x, xhi, xlo);
    }
    tsplit16<<<dim3(DIM / 32, DIM / 32), dim3(32, 8)>>>(Wq, wqth, wqtl, DIM, DIM);
    tsplit16<<<dim3(DIM / 32, DIM / 32), dim3(32, 8)>>>(Wk, wkth, wktl, DIM, DIM);
    t16<<<dim3(2 * HID / 32, DIM / 32), dim3(32, 8)>>>(fc1, fc1t, DIM, 2 * HID);
    t16<<<dim3(DIM / 32, HID / 32), dim3(32, 8)>>>(fc2, fc2t, HID, DIM);

    // ---- q, k via 3-term fp16 split GEMM (sign-critical path) ----
    gemm16<64, true, false, 3><<<(T_TOK / 128) * (DIM / 64), 256, SMEM_QK>>>(
        xhi, xlo, wqth, wqtl, nullptr, q, nullptr, DIM, DIM, T_TOK / 128);
    gemm16<64, true, false, 3><<<(T_TOK / 128) * (DIM / 64), 256, SMEM_QK>>>(
        xhi, xlo, wkth, wktl, nullptr, k, nullptr, DIM, DIM, T_TOK / 128);

    // boundary statistics and scan coefficients
    qkstats_kernel<<<T_TOK, 256>>>(q, k, nq, nk, dqk);
    pcoef_kernel<<<T_TOK / 256, 256>>>(nq, nk, dqk, cu, nseq, a, c);

    // xn = rmsnorm(x)  (fp16)
    rmsnorm_kernel<<<T_TOK, 256>>>(x, norm_w, xn);

    // s = silu(xn@fc1_g) * (xn@fc1_h)   -- fused fc1 + SwiGLU (fp16 out)
    gemm16<64, false, true, 4><<<(T_TOK / 128) * (HID / 64), 256, SMEM_G>>>(
        xn, nullptr, fc1t, nullptr, nullptr, nullptr, s, HID, DIM, T_TOK / 128);

    // z = x + s @ fc2  (fp32 out)
    gemm16<128, false, false, 4><<<(T_TOK / 128) * (DIM / 128), 256, SMEM_G>>>(
        s, nullptr, fc2t, nullptr, x, z, nullptr, DIM, HID, T_TOK / 128);

    // segmented EMA scan -> out
    ema_scan_kernel<<<dim3(DIM / 256, nseq), 256>>>(z, a, c, cu, out);
}